// round 15
// baseline (speedup 1.0000x reference)
#include <cuda_runtime.h>

#define BSZ 2048
#define LSZ 200
#define DSZ 256

// Packed dual-FMA: d = a*b + d elementwise on two packed fp32 (sm_103a FFMA2).
#define FMA_F32X2(acc, a, b) \
    asm("fma.rn.f32x2 %0, %1, %2, %0;" : "+l"(acc) : "l"(a), "l"(b))

// Scratch (device globals — no allocation allowed).
__device__ float g_M[DSZ * DSZ];     // M = W_query @ W_key^T
__device__ float g_QK[BSZ * DSZ];    // q @ M
__device__ float g_CTX[BSZ * DSZ];   // softmax-weighted sum of k rows

// ---------------------------------------------------------------------------
// g_M[i][j] = Wq[i,:] . Wk[j,:]
// grid = 256 CTAs (one per output row i), 8 warps, warp w covers 32 cols.
// ---------------------------------------------------------------------------
__global__ void wmat_kernel(const float* __restrict__ Wq,
                            const float* __restrict__ Wk)
{
    const int i = blockIdx.x;
    const int w = threadIdx.x >> 5;
    const int lane = threadIdx.x & 31;

    const float4* ap = (const float4*)(Wq + i * 256 + lane * 8);
    const float4 a0 = ap[0];
    const float4 a1 = ap[1];

    float res = 0.0f;
    #pragma unroll 4
    for (int jj = 0; jj < 32; jj++) {
        const int j = w * 32 + jj;
        const float4* bp = (const float4*)(Wk + j * 256 + lane * 8);
        const float4 b0 = __ldg(bp);
        const float4 b1 = __ldg(bp + 1);
        float d = a0.x * b0.x + a0.y * b0.y + a0.z * b0.z + a0.w * b0.w
                + a1.x * b1.x + a1.y * b1.y + a1.z * b1.z + a1.w * b1.w;
        #pragma unroll
        for (int off = 16; off > 0; off >>= 1)
            d += __shfl_xor_sync(0xffffffffu, d, off);
        if (lane == jj) res = d;
    }
    g_M[i * 256 + w * 32 + lane] = res;
}

// ---------------------------------------------------------------------------
// Double-buffered FFMA2 tiled GEMM: C[2048,256] = A[2048,256] @ B[256,256]
// BM=32, BN=64, BK=32, 256 threads, micro 2x4, grid (64,4)=256 CTAs.
// A stored DUPLICATED in smem: As[k][2m..2m+1] = (a,a), so one LDS.128
// yields (a0,a0,a1,a1) -- both rows pre-packed for fma.rn.f32x2. B's
// float4 is two f32x2 pairs as-is. Per kk-step: 2x LDS.128 + 4 FFMA2
// = 16 FMA in 6 instructions (scalar version needed 8 FFMA + 2 LDS).
// ---------------------------------------------------------------------------
#define GM_BM 32
#define GM_BN 64
#define GM_BK 32
#define GM_AP 68    // As row stride in floats (272B, 16B-aligned)

__device__ __forceinline__ void tgemm_body(const float* __restrict__ A,
                                           const float* __restrict__ B,
                                           float* __restrict__ C)
{
    __shared__ __align__(16) float As[2][GM_BK][GM_AP];  // [k][2m] duplicated
    __shared__ __align__(16) float Bs[2][GM_BK][GM_BN];  // [k][n]

    const int tid = threadIdx.x;
    const int row0 = blockIdx.x * GM_BM;
    const int col0 = blockIdx.y * GM_BN;

    // global load mapping (256 threads)
    const int ar = tid >> 3;              // 0..31 (A row)
    const int ak = (tid & 7) * 4;         // 0..28 (A k-offset, float4)
    const int bk = tid >> 4;              // 0..15 (B k base; +16 for 2nd)
    const int bc = (tid & 15) * 4;        // 0..60 (B col, float4)

    const float* Ap = A + (size_t)(row0 + ar) * DSZ + ak;
    const float* Bp = B + (size_t)bk * DSZ + col0 + bc;

    // compute mapping: 2 rows x 4 cols per thread
    const int ty = tid >> 4;              // 0..15 -> rows ty*2, ty*2+1
    const int tx = tid & 15;              // 0..15 -> cols tx*4..tx*4+3

    unsigned long long acc00 = 0ull, acc01 = 0ull;  // row0: cols (0,1),(2,3)
    unsigned long long acc10 = 0ull, acc11 = 0ull;  // row1

    // ---- preload chunk 0 into buffer 0
    float4 a0 = __ldg((const float4*)Ap);
    float4 b0 = __ldg((const float4*)Bp);
    float4 b1 = __ldg((const float4*)(Bp + (size_t)16 * DSZ));

    *(float2*)&As[0][ak + 0][ar * 2] = make_float2(a0.x, a0.x);
    *(float2*)&As[0][ak + 1][ar * 2] = make_float2(a0.y, a0.y);
    *(float2*)&As[0][ak + 2][ar * 2] = make_float2(a0.z, a0.z);
    *(float2*)&As[0][ak + 3][ar * 2] = make_float2(a0.w, a0.w);
    *(float4*)&Bs[0][bk][bc]      = b0;
    *(float4*)&Bs[0][bk + 16][bc] = b1;
    __syncthreads();

    int buf = 0;
    #pragma unroll 1
    for (int c = 0; c < DSZ / GM_BK; c++) {
        const bool more = (c + 1 < DSZ / GM_BK);
        if (more) {
            const float* Ap2 = Ap + (c + 1) * GM_BK;
            const float* Bp2 = Bp + (size_t)(c + 1) * GM_BK * DSZ;
            a0 = __ldg((const float4*)Ap2);
            b0 = __ldg((const float4*)Bp2);
            b1 = __ldg((const float4*)(Bp2 + (size_t)16 * DSZ));
        }

        #pragma unroll
        for (int kk = 0; kk < GM_BK; kk++) {
            const ulonglong2 av = *(const ulonglong2*)&As[buf][kk][ty * 4];
            const ulonglong2 bv = *(const ulonglong2*)&Bs[buf][kk][tx * 4];
            FMA_F32X2(acc00, av.x, bv.x);
            FMA_F32X2(acc01, av.x, bv.y);
            FMA_F32X2(acc10, av.y, bv.x);
            FMA_F32X2(acc11, av.y, bv.y);
        }

        if (more) {
            const int nb = buf ^ 1;       // freed by the previous barrier
            *(float2*)&As[nb][ak + 0][ar * 2] = make_float2(a0.x, a0.x);
            *(float2*)&As[nb][ak + 1][ar * 2] = make_float2(a0.y, a0.y);
            *(float2*)&As[nb][ak + 2][ar * 2] = make_float2(a0.z, a0.z);
            *(float2*)&As[nb][ak + 3][ar * 2] = make_float2(a0.w, a0.w);
            *(float4*)&Bs[nb][bk][bc]      = b0;
            *(float4*)&Bs[nb][bk + 16][bc] = b1;
        }
        __syncthreads();
        buf ^= 1;
    }

    const float2 c00 = *(const float2*)&acc00;
    const float2 c01 = *(const float2*)&acc01;
    const float2 c10 = *(const float2*)&acc10;
    const float2 c11 = *(const float2*)&acc11;

    float* Cp = C + (size_t)(row0 + ty * 2) * DSZ + col0 + tx * 4;
    *(float4*)(Cp)       = make_float4(c00.x, c00.y, c01.x, c01.y);
    *(float4*)(Cp + DSZ) = make_float4(c10.x, c10.y, c11.x, c11.y);
}

// QK = q @ g_M
__global__ void __launch_bounds__(256)
qk_gemm_kernel(const float* __restrict__ q)
{
    tgemm_body(q, g_M, g_QK);
}

// out = g_CTX @ Wv
__global__ void __launch_bounds__(256)
out_gemm_kernel(const float* __restrict__ Wv,
                float* __restrict__ out)
{
    tgemm_body(g_CTX, Wv, out);
}

// ---------------------------------------------------------------------------
// Attention in k-space. One CTA per batch (grid 2048, ~3.5 waves -> HW
// load-balancing over variable len). Reads ONLY the first nrows rows:
// masked rows have p == exp(PAD/16 - 1/16) == +0.0f exactly -> contribute
// nothing to Z or CTX. len==0 -> all-PAD -> uniform weights over 200 rows.
// Fixed-max softmax is exact (valid logits = sigmoid/16 in (0, 1/16]).
// Mainloop: 3 rows per outer step -> 6 LDG.128 in flight per warp.
// ---------------------------------------------------------------------------
__global__ void __launch_bounds__(256, 4)
attn_kernel(const float* __restrict__ K,
            const int* __restrict__ keys_length,
            const float* __restrict__ bias)
{
    __shared__ float sZ[8];
    __shared__ float sctx[8][DSZ];

    const int tid = threadIdx.x;
    const int w = tid >> 5;
    const int lane = tid & 31;
    const int b = blockIdx.x;

    const float* kb = K + (size_t)b * LSZ * DSZ;
    const float4* qkp = (const float4*)(g_QK + (size_t)b * DSZ + lane * 8);
    const float4 q0 = qkp[0];
    const float4 q1 = qkp[1];

    const int len = keys_length[b];
    const bool uniform = (len == 0);
    const int nrows = uniform ? LSZ : len;
    const float b256 = bias[0] * 256.0f;

    // warp w owns rows l = w, w+8, w+16, ...
    const int nit = (nrows > w) ? ((nrows - w + 7) >> 3) : 0;
    const float* rp = kb + (size_t)w * DSZ + lane * 8;
    const size_t rstep = (size_t)8 * DSZ;

    float Z = 0.0f;
    float c0 = 0.f, c1 = 0.f, c2 = 0.f, c3 = 0.f;
    float c4 = 0.f, c5 = 0.f, c6 = 0.f, c7 = 0.f;

    int i = 0;
    #pragma unroll 1
    for (; i + 3 <= nit; i += 3) {
        const float4 x0 = __ldg((const float4*)rp);
        const float4 y0 = __ldg((const float4*)rp + 1);
        const float4 x1 = __ldg((const float4*)(rp + rstep));
        const float4 y1 = __ldg((const float4*)(rp + rstep) + 1);
        const float4 x2 = __ldg((const float4*)(rp + 2 * rstep));
        const float4 y2 = __ldg((const float4*)(rp + 2 * rstep) + 1);
        rp += 3 * rstep;

        float d0 = x0.x * q0.x + x0.y * q0.y + x0.z * q0.z + x0.w * q0.w
                 + y0.x * q1.x + y0.y * q1.y + y0.z * q1.z + y0.w * q1.w;
        float d1 = x1.x * q0.x + x1.y * q0.y + x1.z * q0.z + x1.w * q0.w
                 + y1.x * q1.x + y1.y * q1.y + y1.z * q1.z + y1.w * q1.w;
        float d2 = x2.x * q0.x + x2.y * q0.y + x2.z * q0.z + x2.w * q0.w
                 + y2.x * q1.x + y2.y * q1.y + y2.z * q1.z + y2.w * q1.w;
        #pragma unroll
        for (int off = 16; off > 0; off >>= 1) {
            d0 += __shfl_xor_sync(0xffffffffu, d0, off);
            d1 += __shfl_xor_sync(0xffffffffu, d1, off);
            d2 += __shfl_xor_sync(0xffffffffu, d2, off);
        }

        float p0, p1, p2;
        if (uniform) {
            p0 = p1 = p2 = 1.0f;
        } else {
            const float s0 = 1.0f / (1.0f + __expf(-(d0 + b256)));
            const float s1 = 1.0f / (1.0f + __expf(-(d1 + b256)));
            const float s2 = 1.0f / (1.0f + __expf(-(d2 + b256)));
            p0 = __expf(s0 * 0.0625f - 0.0625f);
            p1 = __expf(s1 * 0.0625f - 0.0625f);
            p2 = __expf(s2 * 0.0625f - 0.0625f);
        }

        Z += p0 + p1 + p2;
        c0 += p0 * x0.x + p1 * x1.x + p2 * x2.x;
        c1 += p0 * x0.y + p1 * x1.y + p2 * x2.y;
        c2 += p0 * x0.z + p1 * x1.z + p2 * x2.z;
        c3 += p0 * x0.w + p1 * x1.w + p2 * x2.w;
        c4 += p0 * y0.x + p1 * y1.x + p2 * y2.x;
        c5 += p0 * y0.y + p1 * y1.y + p2 * y2.y;
        c6 += p0 * y0.z + p1 * y1.z + p2 * y2.z;
        c7 += p0 * y0.w + p1 * y1.w + p2 * y2.w;
    }
    #pragma unroll 1
    for (; i < nit; i++) {
        const float4 x0 = __ldg((const float4*)rp);
        const float4 y0 = __ldg((const float4*)rp + 1);
        rp += rstep;
        float d0 = x0.x * q0.x + x0.y * q0.y + x0.z * q0.z + x0.w * q0.w
                 + y0.x * q1.x + y0.y * q1.y + y0.z * q1.z + y0.w * q1.w;
        #pragma unroll
        for (int off = 16; off > 0; off >>= 1)
            d0 += __shfl_xor_sync(0xffffffffu, d0, off);
        float p0;
        if (uniform) {
            p0 = 1.0f;
        } else {
            const float s0 = 1.0f / (1.0f + __expf(-(d0 + b256)));
            p0 = __expf(s0 * 0.0625f - 0.0625f);
        }
        Z += p0;
        c0 += p0 * x0.x; c1 += p0 * x0.y; c2 += p0 * x0.z; c3 += p0 * x0.w;
        c4 += p0 * y0.x; c5 += p0 * y0.y; c6 += p0 * y0.z; c7 += p0 * y0.w;
    }

    if (lane == 0) sZ[w] = Z;   // Z identical across lanes after butterfly
    const int d = lane * 8;
    sctx[w][d + 0] = c0; sctx[w][d + 1] = c1;
    sctx[w][d + 2] = c2; sctx[w][d + 3] = c3;
    sctx[w][d + 4] = c4; sctx[w][d + 5] = c5;
    sctx[w][d + 6] = c6; sctx[w][d + 7] = c7;
    __syncthreads();

    float zt = 0.0f;
    #pragma unroll
    for (int ww = 0; ww < 8; ww++) zt += sZ[ww];
    float c = 0.0f;
    #pragma unroll
    for (int ww = 0; ww < 8; ww++) c += sctx[ww][tid];

    g_CTX[(size_t)b * DSZ + tid] = c / zt;
}

// ---------------------------------------------------------------------------
extern "C" void kernel_launch(void* const* d_in, const int* in_sizes, int n_in,
                              void* d_out, int out_size)
{
    const float* q      = (const float*)d_in[0];   // [2048, 1, 256]
    const float* k      = (const float*)d_in[1];   // [2048, 200, 256]
    // d_in[2] = v: unused (reference derives both score and value paths from k)
    const int*   klen   = (const int*)d_in[3];     // [2048, 1]
    const float* Wq     = (const float*)d_in[4];   // [256, 256]
    const float* Wk     = (const float*)d_in[5];   // [256, 256]
    const float* Wv     = (const float*)d_in[6];   // [256, 256]
    const float* bias   = (const float*)d_in[7];   // [1]
    float* out = (float*)d_out;                    // [2048, 1, 256]

    // 1) M = Wq @ Wk^T
    wmat_kernel<<<256, 256>>>(Wq, Wk);
    // 2) QK = q @ M
    qk_gemm_kernel<<<dim3(BSZ / GM_BM, DSZ / GM_BN), 256>>>(q);
    // 3) attention in k-space (reads only valid rows)
    attn_kernel<<<BSZ, 256>>>(k, klen, bias);
    // 4) out = CTX @ Wv
    out_gemm_kernel<<<dim3(BSZ / GM_BM, DSZ / GM_BN), 256>>>(Wv, out);
}

// round 16
// speedup vs baseline: 1.0298x; 1.0298x over previous
#include <cuda_runtime.h>

#define BSZ 2048
#define LSZ 200
#define DSZ 256

// Scratch (device globals — no allocation allowed).
__device__ float g_M[DSZ * DSZ];     // M = W_query @ W_key^T
__device__ float g_QK[BSZ * DSZ];    // q @ M
__device__ float g_CTX[BSZ * DSZ];   // softmax-weighted sum of k rows

// ---------------------------------------------------------------------------
// g_M[i][j] = Wq[i,:] . Wk[j,:]
// grid = 256 CTAs (one per output row i), 8 warps, warp w covers 32 cols.
// ---------------------------------------------------------------------------
__global__ void wmat_kernel(const float* __restrict__ Wq,
                            const float* __restrict__ Wk)
{
    const int i = blockIdx.x;
    const int w = threadIdx.x >> 5;
    const int lane = threadIdx.x & 31;

    const float4* ap = (const float4*)(Wq + i * 256 + lane * 8);
    const float4 a0 = ap[0];
    const float4 a1 = ap[1];

    float res = 0.0f;
    #pragma unroll 4
    for (int jj = 0; jj < 32; jj++) {
        const int j = w * 32 + jj;
        const float4* bp = (const float4*)(Wk + j * 256 + lane * 8);
        const float4 b0 = __ldg(bp);
        const float4 b1 = __ldg(bp + 1);
        float d = a0.x * b0.x + a0.y * b0.y + a0.z * b0.z + a0.w * b0.w
                + a1.x * b1.x + a1.y * b1.y + a1.z * b1.z + a1.w * b1.w;
        #pragma unroll
        for (int off = 16; off > 0; off >>= 1)
            d += __shfl_xor_sync(0xffffffffu, d, off);
        if (lane == jj) res = d;
    }
    g_M[i * 256 + w * 32 + lane] = res;
}

// ---------------------------------------------------------------------------
// Double-buffered tiled GEMM: C[2048,256] = A[2048,256] @ B[256,256]
// BM=32, BN=64, BK=64, 256 threads, micro 2x4 (scalar FFMA, R14-proven),
// grid (64,4)=256 CTAs. BK=64: only 4 barriers total; 6 global float4
// prefetches in flight across each 64-step compute block.
// ---------------------------------------------------------------------------
#define GM_BM 32
#define GM_BN 64
#define GM_BK 64
#define GM_PAD 34   // As row stride in floats (136B, 8B-aligned for float2)

__device__ __forceinline__ void tgemm_body(const float* __restrict__ A,
                                           const float* __restrict__ B,
                                           float* __restrict__ C)
{
    __shared__ float As[2][GM_BK][GM_PAD];   // [k][m], transposed
    __shared__ float Bs[2][GM_BK][GM_BN];    // [k][n]

    const int tid = threadIdx.x;
    const int row0 = blockIdx.x * GM_BM;
    const int col0 = blockIdx.y * GM_BN;

    // global load mapping (256 threads)
    const int ar = tid >> 3;              // 0..31 (A row)
    const int ak = (tid & 7) * 4;         // 0..28 (A k-offset, float4; +32 2nd)
    const int bk = tid >> 4;              // 0..15 (B k base; +16/+32/+48)
    const int bc = (tid & 15) * 4;        // 0..60 (B col, float4)

    const float* Ap = A + (size_t)(row0 + ar) * DSZ + ak;
    const float* Bp = B + (size_t)bk * DSZ + col0 + bc;

    // compute mapping: 2 rows x 4 cols per thread
    const int ty = tid >> 4;              // 0..15 -> rows ty*2, ty*2+1
    const int tx = tid & 15;              // 0..15 -> cols tx*4..tx*4+3

    float4 acc0 = {0.f,0.f,0.f,0.f};
    float4 acc1 = {0.f,0.f,0.f,0.f};

    // ---- preload chunk 0 into buffer 0
    float4 a0 = __ldg((const float4*)Ap);
    float4 a1 = __ldg((const float4*)(Ap + 32));
    float4 b0 = __ldg((const float4*)Bp);
    float4 b1 = __ldg((const float4*)(Bp + (size_t)16 * DSZ));
    float4 b2 = __ldg((const float4*)(Bp + (size_t)32 * DSZ));
    float4 b3 = __ldg((const float4*)(Bp + (size_t)48 * DSZ));

    As[0][ak + 0][ar] = a0.x; As[0][ak + 1][ar] = a0.y;
    As[0][ak + 2][ar] = a0.z; As[0][ak + 3][ar] = a0.w;
    As[0][ak + 32][ar] = a1.x; As[0][ak + 33][ar] = a1.y;
    As[0][ak + 34][ar] = a1.z; As[0][ak + 35][ar] = a1.w;
    *(float4*)&Bs[0][bk][bc]      = b0;
    *(float4*)&Bs[0][bk + 16][bc] = b1;
    *(float4*)&Bs[0][bk + 32][bc] = b2;
    *(float4*)&Bs[0][bk + 48][bc] = b3;
    __syncthreads();

    int buf = 0;
    #pragma unroll 1
    for (int c = 0; c < DSZ / GM_BK; c++) {
        const bool more = (c + 1 < DSZ / GM_BK);
        if (more) {
            const float* Ap2 = Ap + (c + 1) * GM_BK;
            const float* Bp2 = Bp + (size_t)(c + 1) * GM_BK * DSZ;
            a0 = __ldg((const float4*)Ap2);
            a1 = __ldg((const float4*)(Ap2 + 32));
            b0 = __ldg((const float4*)Bp2);
            b1 = __ldg((const float4*)(Bp2 + (size_t)16 * DSZ));
            b2 = __ldg((const float4*)(Bp2 + (size_t)32 * DSZ));
            b3 = __ldg((const float4*)(Bp2 + (size_t)48 * DSZ));
        }

        #pragma unroll
        for (int kk = 0; kk < GM_BK; kk++) {
            const float2 av = *(const float2*)&As[buf][kk][ty * 2];
            const float4 bv = *(const float4*)&Bs[buf][kk][tx * 4];
            acc0.x += av.x * bv.x; acc0.y += av.x * bv.y;
            acc0.z += av.x * bv.z; acc0.w += av.x * bv.w;
            acc1.x += av.y * bv.x; acc1.y += av.y * bv.y;
            acc1.z += av.y * bv.z; acc1.w += av.y * bv.w;
        }

        if (more) {
            const int nb = buf ^ 1;       // freed by the previous barrier
            As[nb][ak + 0][ar] = a0.x; As[nb][ak + 1][ar] = a0.y;
            As[nb][ak + 2][ar] = a0.z; As[nb][ak + 3][ar] = a0.w;
            As[nb][ak + 32][ar] = a1.x; As[nb][ak + 33][ar] = a1.y;
            As[nb][ak + 34][ar] = a1.z; As[nb][ak + 35][ar] = a1.w;
            *(float4*)&Bs[nb][bk][bc]      = b0;
            *(float4*)&Bs[nb][bk + 16][bc] = b1;
            *(float4*)&Bs[nb][bk + 32][bc] = b2;
            *(float4*)&Bs[nb][bk + 48][bc] = b3;
        }
        __syncthreads();
        buf ^= 1;
    }

    float* Cp = C + (size_t)(row0 + ty * 2) * DSZ + col0 + tx * 4;
    *(float4*)(Cp)       = acc0;
    *(float4*)(Cp + DSZ) = acc1;
}

// QK = q @ g_M
__global__ void __launch_bounds__(256)
qk_gemm_kernel(const float* __restrict__ q)
{
    tgemm_body(q, g_M, g_QK);
}

// out = g_CTX @ Wv
__global__ void __launch_bounds__(256)
out_gemm_kernel(const float* __restrict__ Wv,
                float* __restrict__ out)
{
    tgemm_body(g_CTX, Wv, out);
}

// ---------------------------------------------------------------------------
// Attention in k-space. One CTA per batch (grid 2048, ~3.5 waves -> HW
// load-balancing over variable len). Reads ONLY the first nrows rows:
// masked rows have p == exp(PAD/16 - 1/16) == +0.0f exactly -> contribute
// nothing to Z or CTX. len==0 -> all-PAD -> uniform weights over 200 rows.
// Fixed-max softmax is exact (valid logits = sigmoid/16 in (0, 1/16]).
// Mainloop: 4 rows per outer step -> 8 LDG.128 in flight per warp.
// ---------------------------------------------------------------------------
__global__ void __launch_bounds__(256, 4)
attn_kernel(const float* __restrict__ K,
            const int* __restrict__ keys_length,
            const float* __restrict__ bias)
{
    __shared__ float sZ[8];
    __shared__ float sctx[8][DSZ];

    const int tid = threadIdx.x;
    const int w = tid >> 5;
    const int lane = tid & 31;
    const int b = blockIdx.x;

    const float* kb = K + (size_t)b * LSZ * DSZ;
    const float4* qkp = (const float4*)(g_QK + (size_t)b * DSZ + lane * 8);
    const float4 q0 = qkp[0];
    const float4 q1 = qkp[1];

    const int len = keys_length[b];
    const bool uniform = (len == 0);
    const int nrows = uniform ? LSZ : len;
    const float b256 = bias[0] * 256.0f;

    // warp w owns rows l = w, w+8, w+16, ...
    const int nit = (nrows > w) ? ((nrows - w + 7) >> 3) : 0;
    const float* rp = kb + (size_t)w * DSZ + lane * 8;
    const size_t rstep = (size_t)8 * DSZ;

    float Z = 0.0f;
    float c0 = 0.f, c1 = 0.f, c2 = 0.f, c3 = 0.f;
    float c4 = 0.f, c5 = 0.f, c6 = 0.f, c7 = 0.f;

    int i = 0;
    #pragma unroll 1
    for (; i + 4 <= nit; i += 4) {
        const float4 x0 = __ldg((const float4*)rp);
        const float4 y0 = __ldg((const float4*)rp + 1);
        const float4 x1 = __ldg((const float4*)(rp + rstep));
        const float4 y1 = __ldg((const float4*)(rp + rstep) + 1);
        const float4 x2 = __ldg((const float4*)(rp + 2 * rstep));
        const float4 y2 = __ldg((const float4*)(rp + 2 * rstep) + 1);
        const float4 x3 = __ldg((const float4*)(rp + 3 * rstep));
        const float4 y3 = __ldg((const float4*)(rp + 3 * rstep) + 1);
        rp += 4 * rstep;

        float d0 = x0.x * q0.x + x0.y * q0.y + x0.z * q0.z + x0.w * q0.w
                 + y0.x * q1.x + y0.y * q1.y + y0.z * q1.z + y0.w * q1.w;
        float d1 = x1.x * q0.x + x1.y * q0.y + x1.z * q0.z + x1.w * q0.w
                 + y1.x * q1.x + y1.y * q1.y + y1.z * q1.z + y1.w * q1.w;
        float d2 = x2.x * q0.x + x2.y * q0.y + x2.z * q0.z + x2.w * q0.w
                 + y2.x * q1.x + y2.y * q1.y + y2.z * q1.z + y2.w * q1.w;
        float d3 = x3.x * q0.x + x3.y * q0.y + x3.z * q0.z + x3.w * q0.w
                 + y3.x * q1.x + y3.y * q1.y + y3.z * q1.z + y3.w * q1.w;
        #pragma unroll
        for (int off = 16; off > 0; off >>= 1) {
            d0 += __shfl_xor_sync(0xffffffffu, d0, off);
            d1 += __shfl_xor_sync(0xffffffffu, d1, off);
            d2 += __shfl_xor_sync(0xffffffffu, d2, off);
            d3 += __shfl_xor_sync(0xffffffffu, d3, off);
        }

        float p0, p1, p2, p3;
        if (uniform) {
            p0 = p1 = p2 = p3 = 1.0f;
        } else {
            const float s0 = 1.0f / (1.0f + __expf(-(d0 + b256)));
            const float s1 = 1.0f / (1.0f + __expf(-(d1 + b256)));
            const float s2 = 1.0f / (1.0f + __expf(-(d2 + b256)));
            const float s3 = 1.0f / (1.0f + __expf(-(d3 + b256)));
            p0 = __expf(s0 * 0.0625f - 0.0625f);
            p1 = __expf(s1 * 0.0625f - 0.0625f);
            p2 = __expf(s2 * 0.0625f - 0.0625f);
            p3 = __expf(s3 * 0.0625f - 0.0625f);
        }

        Z += p0 + p1 + p2 + p3;
        c0 += p0 * x0.x + p1 * x1.x + p2 * x2.x + p3 * x3.x;
        c1 += p0 * x0.y + p1 * x1.y + p2 * x2.y + p3 * x3.y;
        c2 += p0 * x0.z + p1 * x1.z + p2 * x2.z + p3 * x3.z;
        c3 += p0 * x0.w + p1 * x1.w + p2 * x2.w + p3 * x3.w;
        c4 += p0 * y0.x + p1 * y1.x + p2 * y2.x + p3 * y3.x;
        c5 += p0 * y0.y + p1 * y1.y + p2 * y2.y + p3 * y3.y;
        c6 += p0 * y0.z + p1 * y1.z + p2 * y2.z + p3 * y3.z;
        c7 += p0 * y0.w + p1 * y1.w + p2 * y2.w + p3 * y3.w;
    }
    #pragma unroll 1
    for (; i < nit; i++) {
        const float4 x0 = __ldg((const float4*)rp);
        const float4 y0 = __ldg((const float4*)rp + 1);
        rp += rstep;
        float d0 = x0.x * q0.x + x0.y * q0.y + x0.z * q0.z + x0.w * q0.w
                 + y0.x * q1.x + y0.y * q1.y + y0.z * q1.z + y0.w * q1.w;
        #pragma unroll
        for (int off = 16; off > 0; off >>= 1)
            d0 += __shfl_xor_sync(0xffffffffu, d0, off);
        float p0;
        if (uniform) {
            p0 = 1.0f;
        } else {
            const float s0 = 1.0f / (1.0f + __expf(-(d0 + b256)));
            p0 = __expf(s0 * 0.0625f - 0.0625f);
        }
        Z += p0;
        c0 += p0 * x0.x; c1 += p0 * x0.y; c2 += p0 * x0.z; c3 += p0 * x0.w;
        c4 += p0 * y0.x; c5 += p0 * y0.y; c6 += p0 * y0.z; c7 += p0 * y0.w;
    }

    if (lane == 0) sZ[w] = Z;   // Z identical across lanes after butterfly
    const int d = lane * 8;
    sctx[w][d + 0] = c0; sctx[w][d + 1] = c1;
    sctx[w][d + 2] = c2; sctx[w][d + 3] = c3;
    sctx[w][d + 4] = c4; sctx[w][d + 5] = c5;
    sctx[w][d + 6] = c6; sctx[w][d + 7] = c7;
    __syncthreads();

    float zt = 0.0f;
    #pragma unroll
    for (int ww = 0; ww < 8; ww++) zt += sZ[ww];
    float c = 0.0f;
    #pragma unroll
    for (int ww = 0; ww < 8; ww++) c += sctx[ww][tid];

    g_CTX[(size_t)b * DSZ + tid] = c / zt;
}

// ---------------------------------------------------------------------------
extern "C" void kernel_launch(void* const* d_in, const int* in_sizes, int n_in,
                              void* d_out, int out_size)
{
    const float* q      = (const float*)d_in[0];   // [2048, 1, 256]
    const float* k      = (const float*)d_in[1];   // [2048, 200, 256]
    // d_in[2] = v: unused (reference derives both score and value paths from k)
    const int*   klen   = (const int*)d_in[3];     // [2048, 1]
    const float* Wq     = (const float*)d_in[4];   // [256, 256]
    const float* Wk     = (const float*)d_in[5];   // [256, 256]
    const float* Wv     = (const float*)d_in[6];   // [256, 256]
    const float* bias   = (const float*)d_in[7];   // [1]
    float* out = (float*)d_out;                    // [2048, 1, 256]

    // 1) M = Wq @ Wk^T
    wmat_kernel<<<256, 256>>>(Wq, Wk);
    // 2) QK = q @ M
    qk_gemm_kernel<<<dim3(BSZ / GM_BM, DSZ / GM_BN), 256>>>(q);
    // 3) attention in k-space (reads only valid rows)
    attn_kernel<<<BSZ, 256>>>(k, klen, bias);
    // 4) out = CTX @ Wv
    out_gemm_kernel<<<dim3(BSZ / GM_BM, DSZ / GM_BN), 256>>>(Wv, out);
}